// round 15
// baseline (speedup 1.0000x reference)
#include <cuda_runtime.h>
#include <cuda_bf16.h>
#include <math.h>

// H = [[1.2, c],[c, 0.01]], c = cos(theta)
// inv = 1/(1.2*0.01 - c^2) * [[0.01, -c],[-c, 1.2]]
//
// Numerics (verified, rel_err 1.92e-5): bulk = __cosf + rcp.approx;
// near-singular elements (|det| < 1e-5, ~0.005%) redo with correctly-rounded
// fp32 cos (via fp64) + correctly-rounded divide — they own the ref L2 norm.
//
// Structure = R8/R13 (empirical optimum) with ONE change: CTA size 256 -> 512.
// Rationale (B300 multi-CTA spread law): spr = 1.10 + 25*(oe*MLP_p1 - 16)/T_CTA.
//   256thr CTAs: oe=8, MLP_p1=4 -> oe*MLP=32 >> 16 -> cross-CTA L1tex-queue
//   spread ~1.2-1.3x. 512thr CTAs: oe=4 -> oe*MLP=16 = threshold -> spread
//   floor ~1.10. Warp-level memory shape (128B coalesced loads, paced 512B
//   STG.128 stores, per-warp MLP=4) is byte-identical to the proven kernel.
//
// History: R7 35.3 | R8 29.9 | R9(MLP8) 31.5 | R10(persist) 33.2 |
//          R11(store burst) 31.2 | R12(=R8) 30.8 | R13(+__ldcs) 29.6 BEST

__device__ __forceinline__ float rcp_approx(float x) {
    float r;
    asm("rcp.approx.f32 %0, %1;" : "=f"(r) : "f"(x));
    return r;
}

__device__ __forceinline__ float4 invert_one(float t)
{
    const float ad = 1.2f * 0.01f;

    float c   = __cosf(t);
    float det = __fsub_rn(ad, __fmul_rn(c, c));
    float r   = rcp_approx(det);

    if (fabsf(det) < 1e-5f) {                 // ~0.005% of elements
        c   = (float)cos((double)t);
        det = __fsub_rn(ad, __fmul_rn(c, c));
        r   = __fdiv_rn(1.0f, det);
    }

    float4 v;
    v.x = __fmul_rn(0.01f, r);
    v.y = __fmul_rn(-c,    r);
    v.z = v.y;
    v.w = __fmul_rn(1.2f,  r);
    return v;
}

__global__ __launch_bounds__(512) void inv2x2_kernel_v14(
    const float* __restrict__ theta,
    float4* __restrict__ out,
    int n)
{
    const int T = 512;                         // blockDim.x
    int base = blockIdx.x * (T * 4) + threadIdx.x;

    if (base + 3 * T < n) {
        // Front-batched independent loads: 4 LDGs in flight per warp before
        // any compute (MLP_p1 = 4), each a coalesced 128B warp load.
        // Evict-first: input is read exactly once.
        float t0 = __ldcs(&theta[base]);
        float t1 = __ldcs(&theta[base +     T]);
        float t2 = __ldcs(&theta[base + 2 * T]);
        float t3 = __ldcs(&theta[base + 3 * T]);

        // Compute + store interleaved; each store is a coalesced 512B/warp
        // STG.128 spaced between MUFU chains (store pacing is load-bearing).
        out[base]         = invert_one(t0);
        out[base +     T] = invert_one(t1);
        out[base + 2 * T] = invert_one(t2);
        out[base + 3 * T] = invert_one(t3);
    } else {
        // Tail (unused for n = 8388608, divisible by 2048).
        for (int k = 0; k < 4; k++) {
            int i = base + k * T;
            if (i < n) out[i] = invert_one(__ldcs(&theta[i]));
        }
    }
}

extern "C" void kernel_launch(void* const* d_in, const int* in_sizes, int n_in,
                              void* d_out, int out_size) {
    const float* theta = (const float*)d_in[0];
    float4* out = (float4*)d_out;
    int n = in_sizes[0];                       // 8388608

    const int threads = 512;
    int elems_per_block = threads * 4;         // 2048
    int blocks = (n + elems_per_block - 1) / elems_per_block;   // 4096
    inv2x2_kernel_v14<<<blocks, threads>>>(theta, out, n);
}